// round 3
// baseline (speedup 1.0000x reference)
#include <cuda_runtime.h>
#include <math.h>

#define BSZ 8
#define TD  64
#define TE  512
#define HH  512

// Scratch (allocation-free rule: __device__ globals)
__device__ float g_u  [BSZ*TD*HH];   // dec_part + bias
__device__ float g_v  [BSZ*TE*HH];   // enc_part
__device__ float g_Eu [BSZ*TD*HH];   // exp(u - mu)
__device__ float g_Ev [BSZ*TE*HH];   // exp(v - mv)
__device__ float g_mu [BSZ*TD];
__device__ float g_mv [BSZ*TE];
__device__ float g_S1 [BSZ*HH];      // sum_j enc[b,j,d]
__device__ float g_S2 [BSZ*HH];      // sum_j v[b,j,d]*enc[b,j,d]
__device__ float g_lse[BSZ*TD*TE];

// ---------------------------------------------------------------------------
// Generic batched C = A @ B^T (both A and B are K-contiguous row-major).
// 64x64 tile, BK=16, 256 threads, 4x4 per thread.
// MODE 0: C = acc (+ bias[col] if bias != null)
// MODE 1: C = rvec[b*rstride+row] + cvec[b*cstride+col] + logf(acc)   (lse)
// ---------------------------------------------------------------------------
__global__ void __launch_bounds__(256) gemm_abt(
    const float* __restrict__ Abase, int lda, long sA,
    const float* __restrict__ Bbase, int ldb, long sB,
    float* __restrict__ Cbase, int ldc, long sC,
    int K, int MODE,
    const float* __restrict__ bias,
    const float* __restrict__ rvec, int rstride,
    const float* __restrict__ cvec, int cstride)
{
    __shared__ float As[16][64];
    __shared__ float Bs[16][64];

    const int b = blockIdx.z;
    const float* A  = Abase + (long)b * sA + (long)blockIdx.y * 64 * lda;
    const float* Bm = Bbase + (long)b * sB + (long)blockIdx.x * 64 * ldb;

    const int tid = threadIdx.x;
    const int tx = tid & 15, ty = tid >> 4;
    const int lr = tid >> 2;          // 0..63
    const int lc = (tid & 3) << 2;    // 0,4,8,12

    float acc[4][4] = {};

    for (int k0 = 0; k0 < K; k0 += 16) {
        float4 av = *reinterpret_cast<const float4*>(&A [(long)lr*lda + k0 + lc]);
        float4 bv = *reinterpret_cast<const float4*>(&Bm[(long)lr*ldb + k0 + lc]);
        As[lc+0][lr]=av.x; As[lc+1][lr]=av.y; As[lc+2][lr]=av.z; As[lc+3][lr]=av.w;
        Bs[lc+0][lr]=bv.x; Bs[lc+1][lr]=bv.y; Bs[lc+2][lr]=bv.z; Bs[lc+3][lr]=bv.w;
        __syncthreads();
        #pragma unroll
        for (int k = 0; k < 16; ++k) {
            float ar[4], br[4];
            #pragma unroll
            for (int i = 0; i < 4; ++i) { ar[i] = As[k][(ty<<2)+i]; br[i] = Bs[k][(tx<<2)+i]; }
            #pragma unroll
            for (int i = 0; i < 4; ++i)
                #pragma unroll
                for (int j = 0; j < 4; ++j)
                    acc[i][j] = fmaf(ar[i], br[j], acc[i][j]);
        }
        __syncthreads();
    }

    const int rowB = blockIdx.y * 64 + (ty << 2);
    const int colB = blockIdx.x * 64 + (tx << 2);
    float* C = Cbase + (long)b * sC;

    #pragma unroll
    for (int i = 0; i < 4; ++i)
        #pragma unroll
        for (int j = 0; j < 4; ++j) {
            float val = acc[i][j];
            if (MODE == 0) {
                if (bias) val += bias[colB + j];
            } else {
                val = rvec[b*rstride + rowB + i] + cvec[b*cstride + colB + j] + logf(val);
            }
            C[(long)(rowB + i) * ldc + colB + j] = val;
        }
}

// ---------------------------------------------------------------------------
// Final: out[b,i,d] = u[b,i,d]*S1[b,d] + S2[b,d] - sum_j lse[b,i,j]*enc[b,j,d]
// A = lse (64 x 512, j-contiguous), B = enc (512_j x 512_d, d-contiguous): A@B.
// ---------------------------------------------------------------------------
__global__ void __launch_bounds__(256) gemm_ab_final(
    const float* __restrict__ lse,
    const float* __restrict__ enc,
    const float* __restrict__ u,
    const float* __restrict__ S1,
    const float* __restrict__ S2,
    float* __restrict__ out)
{
    __shared__ float As[16][64];
    __shared__ float Bs[16][64];

    const int b = blockIdx.z;
    const float* A  = lse + (long)b * TD * TE + (long)blockIdx.y * 64 * TE;
    const float* Bm = enc + (long)b * TE * HH + blockIdx.x * 64;

    const int tid = threadIdx.x;
    const int tx = tid & 15, ty = tid >> 4;
    const int lr  = tid >> 2;
    const int lc  = (tid & 3) << 2;
    const int bRow  = tid >> 4;         // 0..15
    const int bCol4 = (tid & 15) << 2;  // 0..60

    float acc[4][4] = {};

    for (int k0 = 0; k0 < TE; k0 += 16) {
        float4 av = *reinterpret_cast<const float4*>(&A[(long)lr*TE + k0 + lc]);
        As[lc+0][lr]=av.x; As[lc+1][lr]=av.y; As[lc+2][lr]=av.z; As[lc+3][lr]=av.w;
        float4 bv = *reinterpret_cast<const float4*>(&Bm[(long)(k0 + bRow)*HH + bCol4]);
        *reinterpret_cast<float4*>(&Bs[bRow][bCol4]) = bv;
        __syncthreads();
        #pragma unroll
        for (int k = 0; k < 16; ++k) {
            float ar[4], br[4];
            #pragma unroll
            for (int i = 0; i < 4; ++i) { ar[i] = As[k][(ty<<2)+i]; br[i] = Bs[k][(tx<<2)+i]; }
            #pragma unroll
            for (int i = 0; i < 4; ++i)
                #pragma unroll
                for (int j = 0; j < 4; ++j)
                    acc[i][j] = fmaf(ar[i], br[j], acc[i][j]);
        }
        __syncthreads();
    }

    const int rowB = blockIdx.y * 64 + (ty << 2);
    const int colB = blockIdx.x * 64 + (tx << 2);

    #pragma unroll
    for (int i = 0; i < 4; ++i)
        #pragma unroll
        for (int j = 0; j < 4; ++j) {
            int d = colB + j;
            long idx = (long)b * TD * HH + (long)(rowB + i) * HH + d;
            out[idx] = u[idx] * S1[b*HH + d] + S2[b*HH + d] - acc[i][j];
        }
}

// ---------------------------------------------------------------------------
// Per-row max + exp(x - max). One block (128 thr) per row, ncols = 512.
// ---------------------------------------------------------------------------
__global__ void __launch_bounds__(128) rowmax_exp(
    const float* __restrict__ X, float* __restrict__ E,
    float* __restrict__ Mx, int ncols)
{
    const long row = blockIdx.x;
    const float* x = X + row * ncols;
    const int tid = threadIdx.x;

    float m = -INFINITY;
    for (int c = tid; c < ncols; c += 128) m = fmaxf(m, x[c]);
    #pragma unroll
    for (int o = 16; o; o >>= 1) m = fmaxf(m, __shfl_xor_sync(0xffffffffu, m, o));
    __shared__ float sm[4];
    if ((tid & 31) == 0) sm[tid >> 5] = m;
    __syncthreads();
    m = fmaxf(fmaxf(sm[0], sm[1]), fmaxf(sm[2], sm[3]));
    if (tid == 0) Mx[row] = m;

    float* e = E + row * ncols;
    for (int c = tid; c < ncols; c += 128) e[c] = expf(x[c] - m);
}

// ---------------------------------------------------------------------------
// S1[b,d] = sum_j enc[b,j,d] ; S2[b,d] = sum_j v[b,j,d]*enc[b,j,d]
// ---------------------------------------------------------------------------
__global__ void __launch_bounds__(256) colsum(
    const float* __restrict__ enc, const float* __restrict__ v,
    float* __restrict__ S1, float* __restrict__ S2)
{
    const int b = blockIdx.y;
    const int d = blockIdx.x * blockDim.x + threadIdx.x;
    const float* e  = enc + (long)b * TE * HH;
    const float* vv = v   + (long)b * TE * HH;
    float s1 = 0.f, s2 = 0.f;
    #pragma unroll 4
    for (int j = 0; j < TE; ++j) {
        float ev = e[(long)j*HH + d];
        s1 += ev;
        s2 += vv[(long)j*HH + d] * ev;
    }
    S1[b*HH + d] = s1;
    S2[b*HH + d] = s2;
}

// ---------------------------------------------------------------------------
extern "C" void kernel_launch(void* const* d_in, const int* in_sizes, int n_in,
                              void* d_out, int out_size)
{
    const float *enc = nullptr, *dec = nullptr, *W = nullptr, *bias = nullptr;
    for (int i = 0; i < n_in; ++i) {
        switch (in_sizes[i]) {
            case BSZ*TE*HH: enc  = (const float*)d_in[i]; break;  // 2097152
            case BSZ*TD*HH: dec  = (const float*)d_in[i]; break;  // 262144
            case HH*2*HH:   W    = (const float*)d_in[i]; break;  // 524288
            case HH:        bias = (const float*)d_in[i]; break;  // 512
        }
    }
    float* out = (float*)d_out;

    float *u,*v,*Eu,*Ev,*mu,*mv,*S1,*S2,*lse;
    cudaGetSymbolAddress((void**)&u,   g_u);
    cudaGetSymbolAddress((void**)&v,   g_v);
    cudaGetSymbolAddress((void**)&Eu,  g_Eu);
    cudaGetSymbolAddress((void**)&Ev,  g_Ev);
    cudaGetSymbolAddress((void**)&mu,  g_mu);
    cudaGetSymbolAddress((void**)&mv,  g_mv);
    cudaGetSymbolAddress((void**)&S1,  g_S1);
    cudaGetSymbolAddress((void**)&S2,  g_S2);
    cudaGetSymbolAddress((void**)&lse, g_lse);

    // 1) u = dec @ W_dec^T + bias        (W_dec[o,d] = W[o*1024 + d])
    gemm_abt<<<dim3(HH/64, TD/64, BSZ), 256>>>(
        dec, HH, (long)TD*HH,
        W,   2*HH, 0L,
        u,   HH, (long)TD*HH,
        HH, 0, bias, nullptr, 0, nullptr, 0);

    // 2) v = enc @ W_enc^T               (W_enc[o,d] = W[o*1024 + 512 + d])
    gemm_abt<<<dim3(HH/64, TE/64, BSZ), 256>>>(
        enc, HH, (long)TE*HH,
        W + HH, 2*HH, 0L,
        v,   HH, (long)TE*HH,
        HH, 0, nullptr, nullptr, 0, nullptr, 0);

    // 3) Eu = exp(u - mu), Ev = exp(v - mv)
    rowmax_exp<<<BSZ*TD, 128>>>(u, Eu, mu, HH);
    rowmax_exp<<<BSZ*TE, 128>>>(v, Ev, mv, HH);

    // 4) S1, S2 column sums over j
    colsum<<<dim3(HH/256, BSZ), 256>>>(enc, v, S1, S2);

    // 5) lse[b,i,j] = mu[b,i] + mv[b,j] + log( Eu[b,i,:] . Ev[b,j,:] )
    gemm_abt<<<dim3(TE/64, TD/64, BSZ), 256>>>(
        Eu,  HH, (long)TD*HH,
        Ev,  HH, (long)TE*HH,
        lse, TE, (long)TD*TE,
        HH, 1, nullptr, mu, TD, mv, TE);

    // 6) out = u*S1 + S2 - lse @ enc
    gemm_ab_final<<<dim3(HH/64, TD/64, BSZ), 256>>>(lse, enc, u, S1, S2, out);
}